// round 14
// baseline (speedup 1.0000x reference)
#include <cuda_runtime.h>
#include <cuda_fp16.h>
#include <math.h>
#include <stdint.h>

#define NMAX 50000
#define DOUT 64
#define OSTRIDE 76
#define KCH16 17          // 17 k-chunks of 16 -> K = 272 (265 real + 7 zero pad)
#define KWH 148           // rad/W row stride in 32-bit words (296 halves); 148%32=20
#define NPAIR 15
#define NTHREADS 960

// shared memory offsets (32-bit words)
#define OFF_W 0                     // 64*148        = 9472
#define OFF_RAD 9472                // 240*148       = 35520 -> 44992
#define OFF_ATT 44992               // 30 warps*256  =  7680 -> 52672 (double-buffered)
#define OFF_M 52672                 // 30 warps*32   =   960 -> 53632 (double-buffered)
#define OFF_RINV 53632              // 240 -> 53872
#define OFF_ROW 53872               // 240 -> 54112
#define OFF_BIAS 54112              // 64  -> 54176
#define SMEM_WORDS 54176            // *4 = 216704 bytes (< 227KB limit)

__device__ float g_lf[NMAX * 9];
__device__ float g_pooled[NMAX * 3];
__device__ float g_cnt[NMAX];

// ---------------------------------------------------------------------------
__device__ __forceinline__ void red4(float* p, float a, float b, float c, float d) {
    asm volatile("red.global.add.v4.f32 [%0], {%1,%2,%3,%4};"
                 :: "l"(p), "f"(a), "f"(b), "f"(c), "f"(d) : "memory");
}

// pack two fp32 into one fp16x2 word: lo <- a, hi <- b
__device__ __forceinline__ uint32_t f2h2(float lo, float hi) {
    uint32_t r;
    asm("cvt.rn.f16x2.f32 %0, %1, %2;" : "=r"(r) : "f"(hi), "f"(lo));
    return r;
}

// ---------------------------------------------------------------------------
__global__ void zero_kernel(float* out, int out_n, int n_nodes) {
    int i = blockIdx.x * blockDim.x + threadIdx.x;
    int stride = gridDim.x * blockDim.x;
    for (int k = i; k < out_n; k += stride) out[k] = 0.f;
    for (int k = i; k < n_nodes; k += stride) g_cnt[k] = 0.f;
}

// ---------------------------------------------------------------------------
__global__ void node_kernel(const float* __restrict__ coord,
                            const float* __restrict__ cw, int n) {
    int v = blockIdx.x * blockDim.x + threadIdx.x;
    if (v >= n) return;
    const float* cp = coord + v * 12;
    float cax = cp[0], cay = cp[1], caz = cp[2];
    float ccx = cp[3], ccy = cp[4], ccz = cp[5];
    float nnx = cp[6], nny = cp[7], nnz = cp[8];

    float xx = ccx - cax, xy = ccy - cay, xz = ccz - caz;
    float xn = sqrtf(xx * xx + xy * xy + xz * xz) + 1e-8f;
    xx /= xn; xy /= xn; xz /= xn;

    float tx = nnx - cax, ty = nny - cay, tz = nnz - caz;
    float d = tx * xx + ty * xy + tz * xz;
    float yx = tx - d * xx, yy = ty - d * xy, yz = tz - d * xz;
    float yn = sqrtf(yx * yx + yy * yy + yz * yz) + 1e-8f;
    yx /= yn; yy /= yn; yz /= yn;

    float zx = xy * yz - xz * yy;
    float zy = xz * yx - xx * yz;
    float zz = xx * yy - xy * yx;

    float* L = g_lf + v * 9;
    L[0] = xx; L[1] = yx; L[2] = zx;
    L[3] = xy; L[4] = yy; L[5] = zy;
    L[6] = xz; L[7] = yz; L[8] = zz;

    float px = 0.f, py = 0.f, pz = 0.f, cs = 0.f;
#pragma unroll
    for (int i = 0; i < 4; i++) {
        float m = (cw[v * 4 + i] != 0.f) ? 1.f : 0.f;
        cs += m;
        px += cp[i * 3 + 0] * m;
        py += cp[i * 3 + 1] * m;
        pz += cp[i * 3 + 2] * m;
    }
    g_pooled[v * 3 + 0] = px / cs;
    g_pooled[v * 3 + 1] = py / cs;
    g_pooled[v * 3 + 2] = pz / cs;
}

// ---------------------------------------------------------------------------
__device__ __forceinline__ void mma16(float& d0, float& d1, float& d2, float& d3,
                                      uint32_t a0, uint32_t a1, uint32_t a2, uint32_t a3,
                                      uint32_t b0, uint32_t b1) {
    asm volatile("mma.sync.aligned.m16n8k16.row.col.f32.f16.f16.f32 "
                 "{%0,%1,%2,%3}, {%4,%5,%6,%7}, {%8,%9}, {%0,%1,%2,%3};"
                 : "+f"(d0), "+f"(d1), "+f"(d2), "+f"(d3)
                 : "r"(a0), "r"(a1), "r"(a2), "r"(a3), "r"(b0), "r"(b1));
}

__device__ __forceinline__ void pair_bar(int pair) {
    asm volatile("bar.sync %0, 64;" :: "r"(pair + 1) : "memory");
}

// ---------------------------------------------------------------------------
// 15 independent 2-warp pipelines per CTA; fp16 GEMM operands, fp32 accum.
// k-dimension of the GEMM is permuted (k' = b*16 + a for the 256 radial
// entries) so each lane's 8 radial halves are CONTIGUOUS -> one STS.128.
__global__ void __launch_bounds__(NTHREADS, 1)
edge_kernel(const float* __restrict__ coord, const float* __restrict__ attr,
            const float* __restrict__ cw, const float* __restrict__ W,
            const float* __restrict__ bias, const int* __restrict__ row,
            const int* __restrict__ col, float* __restrict__ out, int E) {
    extern __shared__ float sm[];
    uint32_t* sWw  = (uint32_t*)(sm + OFF_W);      // W fp16: [o][k'word], stride KWH
    __half*   sRadH = (__half*)(sm + OFF_RAD);     // rad fp16: rows of 296 halves
    float* sBias = sm + OFF_BIAS;

    int tid = threadIdx.x, warp = tid >> 5, lane = tid & 31;

    // Stage W (fp16 pairs, [o][k'] layout: k' = b*16+a for k'<256, geo after)
    for (int idx = tid; idx < 64 * 136; idx += NTHREADS) {
        int o = idx / 136, kw = idx % 136;
        int kp0 = 2 * kw, kp1 = 2 * kw + 1;
        float f0 = 0.f, f1 = 0.f;
        if (kp0 < 256)      f0 = W[o * 273 + ((kp0 & 15) * 16 + (kp0 >> 4))];
        else if (kp0 < 265) f0 = W[o * 273 + kp0 + 8];
        if (kp1 < 256)      f1 = W[o * 273 + ((kp1 & 15) * 16 + (kp1 >> 4))];
        else if (kp1 < 265) f1 = W[o * 273 + kp1 + 8];
        __half2 h = __floats2half2_rn(f0, f1);
        sWw[o * KWH + kw] = *(uint32_t*)&h;
    }
    for (int idx = tid; idx < 64 * 12; idx += NTHREADS) {   // W pad words 136..147
        int o = idx / 12, kw = 136 + idx % 12;
        sWw[o * KWH + kw] = 0u;
    }
    // Zero rad k-pad (halves 265..295) ONCE — never overwritten afterwards.
    for (int idx = tid; idx < 240 * 31; idx += NTHREADS) {
        int rrow = idx / 31, kk = 265 + idx % 31;
        sRadH[rrow * 296 + kk] = __ushort_as_half(0);
    }
    if (tid < 64) sBias[tid] = bias[tid];
    __syncthreads();

    const int pair = warp >> 1;         // 0..14
    const int win  = warp & 1;
    const int g = lane >> 2, tig = lane & 3;
    const int b16 = lane & 15, half = lane >> 4;
    const int oh = win * 32;            // this warp's output-column half

    uint32_t* radw   = (uint32_t*)(sm + OFF_RAD) + pair * 16 * KWH;
    __half*   sRadP  = sRadH + pair * 16 * 296;
    float* sRinvP = sm + OFF_RINV + pair * 16;
    int*   sRowP  = (int*)(sm + OFF_ROW) + pair * 16;
    float* sAttW  = sm + OFF_ATT + warp * 256;   // 2 slots x [attr_r(64)|attr_c(64)]
    float* sMW    = sm + OFF_M + warp * 32;      // 2 slots x 16
    const int mi = (lane >> 2) & 3, mj = lane & 3;
    const int hb = 2 * half;            // float4 base for this half's ar rows
    const int wbase = b16 * 8 + half * 4;  // this lane's rad word base (16B aligned)

    int gpair  = blockIdx.x * NPAIR + pair;
    int npairs = gridDim.x * NPAIR;
    int ngroups = (E + 15) >> 4;

    for (int grp = gpair; grp < ngroups; grp += npairs) {
        // wait until the partner warp finished reading rad of the previous group
        pair_bar(pair);

        // ================= phase 1: 8 edges per warp =================
        int e0g = grp * 16 + win * 8;
        int rc = 0;
        {
            int e = e0g + (lane & 7);
            if (e < E) rc = (lane < 16) ? row[e] : col[e];
        }
        if (lane < 8) sRowP[win * 8 + lane] = rc;

        float ssq[8];
#pragma unroll
        for (int h4 = 0; h4 < 2; h4++) {
            // ---- batched prefetch of 4 edges (MLP=4) ----
            float4 av[4];
            float gv[4], lfv[4], pv[4];
            int rr[4];
#pragma unroll
            for (int u = 0; u < 4; u++) {
                int t = h4 * 4 + u;
                int r = __shfl_sync(0xffffffffu, rc, t);
                int c = __shfl_sync(0xffffffffu, rc, 16 + t);
                rr[u] = r;
                int nn = (lane < 16) ? r : c;
                av[u] = __ldg((const float4*)(attr + nn * 64) + b16);
                const float* gp;
                if (lane < 12)      gp = coord + r * 12 + lane;
                else if (lane < 24) gp = coord + c * 12 + (lane - 12);
                else if (lane < 28) gp = cw + r * 4 + (lane - 24);
                else                gp = cw + c * 4 + (lane - 28);
                gv[u] = __ldg(gp);
                lfv[u] = (lane < 9)
                       ? g_lf[r * 9 + lane] + g_lf[c * 9 + lane] : 0.f;
                pv[u] = (lane < 12) ? g_pooled[c * 3 + lane % 3] : 0.f;
            }

            // ---- process the 4 edges (double-buffered staging) ----
#pragma unroll
            for (int u = 0; u < 4; u++) {
                int t = h4 * 4 + u;
                float* slot = sAttW + (t & 1) * 128;
                float* sMs  = sMW + (t & 1) * 16;
                ((float4*)slot)[lane] = av[u];

                float gvu = gv[u];
                float rx = __shfl_sync(0xffffffffu, gvu, 3 * mi);
                float ry = __shfl_sync(0xffffffffu, gvu, 3 * mi + 1);
                float rz = __shfl_sync(0xffffffffu, gvu, 3 * mi + 2);
                float cx = __shfl_sync(0xffffffffu, gvu, 12 + 3 * mj);
                float cy = __shfl_sync(0xffffffffu, gvu, 13 + 3 * mj);
                float cz = __shfl_sync(0xffffffffu, gvu, 14 + 3 * mj);
                float wr = __shfl_sync(0xffffffffu, gvu, 24 + mi);
                float wc = __shfl_sync(0xffffffffu, gvu, 28 + mj);
                if (lane < 16) {
                    float dx = rx - cx, dy = ry - cy, dz = rz - cz;
                    sMs[lane] = sqrtf(dx * dx + dy * dy + dz * dz) * wr * wc;
                }
                __syncwarp();

                // ---- vectorized smem reads: M as 4x LDS.128 ----
                const float4* m4 = (const float4*)sMs;
                float4 M0 = m4[0], M1 = m4[1], M2 = m4[2], M3 = m4[3];

                const float* s_ac = slot + 64;
                float a0 = s_ac[b16], a1 = s_ac[16 + b16];
                float a2 = s_ac[32 + b16], a3 = s_ac[48 + b16];
                float tmp0 = M0.x * a0 + M0.y * a1 + M0.z * a2 + M0.w * a3;
                float tmp1 = M1.x * a0 + M1.y * a1 + M1.z * a2 + M1.w * a3;
                float tmp2 = M2.x * a0 + M2.y * a1 + M2.z * a2 + M2.w * a3;
                float tmp3 = M3.x * a0 + M3.y * a1 + M3.z * a2 + M3.w * a3;

                // ---- ar rows as 8x LDS.128 (broadcast within half) ----
                const float4* slot4 = (const float4*)slot;
                float4 r0a = slot4[hb],      r0b = slot4[hb + 1];
                float4 r1a = slot4[4 + hb],  r1b = slot4[4 + hb + 1];
                float4 r2a = slot4[8 + hb],  r2b = slot4[8 + hb + 1];
                float4 r3a = slot4[12 + hb], r3b = slot4[12 + hb + 1];

                float va[8];
                va[0] = r0a.x * tmp0 + r1a.x * tmp1 + r2a.x * tmp2 + r3a.x * tmp3;
                va[1] = r0a.y * tmp0 + r1a.y * tmp1 + r2a.y * tmp2 + r3a.y * tmp3;
                va[2] = r0a.z * tmp0 + r1a.z * tmp1 + r2a.z * tmp2 + r3a.z * tmp3;
                va[3] = r0a.w * tmp0 + r1a.w * tmp1 + r2a.w * tmp2 + r3a.w * tmp3;
                va[4] = r0b.x * tmp0 + r1b.x * tmp1 + r2b.x * tmp2 + r3b.x * tmp3;
                va[5] = r0b.y * tmp0 + r1b.y * tmp1 + r2b.y * tmp2 + r3b.y * tmp3;
                va[6] = r0b.z * tmp0 + r1b.z * tmp1 + r2b.z * tmp2 + r3b.z * tmp3;
                va[7] = r0b.w * tmp0 + r1b.w * tmp1 + r2b.w * tmp2 + r3b.w * tmp3;

                // ---- packed radial writeout: 4x cvt.f16x2 + one STS.128 ----
                uint32_t* rw = radw + (win * 8 + t) * KWH;
                uint4 pk;
                pk.x = f2h2(va[0], va[1]);
                pk.y = f2h2(va[2], va[3]);
                pk.z = f2h2(va[4], va[5]);
                pk.w = f2h2(va[6], va[7]);
                *(uint4*)(rw + wbase) = pk;

                float part = va[0]*va[0] + va[1]*va[1] + va[2]*va[2] + va[3]*va[3]
                           + va[4]*va[4] + va[5]*va[5] + va[6]*va[6] + va[7]*va[7];

                __half* rrow = sRadP + (win * 8 + t) * 296;
                if (lane < 9) {
                    rrow[256 + lane] = __float2half_rn(lfv[u]);
                    part += lfv[u] * lfv[u];
                }
                ssq[t] = part;

                // ---- coord aggregation: pack 12 diffs into 3 red.v4 + cnt ----
                float dco = (lane < 12) ? (gvu - pv[u]) : 0.f;
                float q0 = __shfl_sync(0xffffffffu, dco, (4 * lane) & 31);
                float q1 = __shfl_sync(0xffffffffu, dco, (4 * lane + 1) & 31);
                float q2 = __shfl_sync(0xffffffffu, dco, (4 * lane + 2) & 31);
                float q3 = __shfl_sync(0xffffffffu, dco, (4 * lane + 3) & 31);
                if (e0g + t < E) {
                    if (lane < 3)
                        red4(out + rr[u] * OSTRIDE + 64 + 4 * lane, q0, q1, q2, q3);
                    else if (lane == 3)
                        atomicAdd(&g_cnt[rr[u]], 1.f);
                }
            }
        }

        // deferred reductions: 8 independent shuffle trees, pipelined
#pragma unroll
        for (int t = 0; t < 8; t++) {
            float s = ssq[t];
            s += __shfl_xor_sync(0xffffffffu, s, 16);
            s += __shfl_xor_sync(0xffffffffu, s, 8);
            s += __shfl_xor_sync(0xffffffffu, s, 4);
            s += __shfl_xor_sync(0xffffffffu, s, 2);
            s += __shfl_xor_sync(0xffffffffu, s, 1);
            if (lane == t) sRinvP[win * 8 + t] = __frcp_rn(sqrtf(s) + 1.f);
        }
        pair_bar(pair);   // rad/rinv/row of both warps visible to the pair

        // ===== phase 2: fp16 MMA (m16n8k16), 16 edges x 32 outs per warp ====
        float acc[4][4];
#pragma unroll
        for (int n = 0; n < 4; n++)
#pragma unroll
            for (int q = 0; q < 4; q++) acc[n][q] = 0.f;

        const uint32_t* aB = radw + g * KWH + tig;
        const uint32_t* bB = sWw + (oh + g) * KWH + tig;

#pragma unroll 2
        for (int kc = 0; kc < KCH16; kc++) {
            int k0 = kc * 8;
            uint32_t A0 = aB[k0];
            uint32_t A1 = aB[8 * KWH + k0];
            uint32_t A2 = aB[k0 + 4];
            uint32_t A3 = aB[8 * KWH + k0 + 4];
            uint32_t B[4][2];
#pragma unroll
            for (int n = 0; n < 4; n++) {
                B[n][0] = bB[(n * 8) * KWH + k0];
                B[n][1] = bB[(n * 8) * KWH + k0 + 4];
            }
#pragma unroll
            for (int n = 0; n < 4; n++)
                mma16(acc[n][0], acc[n][1], acc[n][2], acc[n][3],
                      A0, A1, A2, A3, B[n][0], B[n][1]);
        }

        // ====== epilogue: (acc + b) * rinv -> paired red.v4 scatter ==========
        {
            int el0 = g, el1 = 8 + g;
            bool v0 = (grp * 16 + el0) < E;
            bool v1 = (grp * 16 + el1) < E;
            float ri0 = sRinvP[el0], ri1 = sRinvP[el1];
            float* ob0 = out + sRowP[el0] * OSTRIDE;
            float* ob1 = out + sRowP[el1] * OSTRIDE;
            bool emit = ((tig & 1) == 0);
#pragma unroll
            for (int n = 0; n < 4; n++) {
                int o = oh + n * 8 + 2 * tig;
                float bo0 = sBias[o], bo1 = sBias[o + 1];
                float x0 = (acc[n][0] + bo0) * ri0;
                float x1 = (acc[n][1] + bo1) * ri0;
                float z0 = (acc[n][2] + bo0) * ri1;
                float z1 = (acc[n][3] + bo1) * ri1;
                float px0 = __shfl_xor_sync(0xffffffffu, x0, 1);
                float px1 = __shfl_xor_sync(0xffffffffu, x1, 1);
                float pz0 = __shfl_xor_sync(0xffffffffu, z0, 1);
                float pz1 = __shfl_xor_sync(0xffffffffu, z1, 1);
                if (emit) {
                    if (v0) red4(ob0 + o, x0, x1, px0, px1);
                    if (v1) red4(ob1 + o, z0, z1, pz0, pz1);
                }
            }
        }
    }
}

// ---------------------------------------------------------------------------
__global__ void finalize_kernel(float* out, int n) {
    int v = blockIdx.x * blockDim.x + threadIdx.x;
    if (v >= n) return;
    float cf = 1.f / fmaxf(g_cnt[v], 1.f);
    float* p = out + v * OSTRIDE + 64;
#pragma unroll
    for (int d = 0; d < 12; d++) p[d] *= cf;
}

// ---------------------------------------------------------------------------
extern "C" void kernel_launch(void* const* d_in, const int* in_sizes, int n_in,
                              void* d_out, int out_size) {
    const float* coord = (const float*)d_in[0];
    const float* attr  = (const float*)d_in[1];
    const float* cw    = (const float*)d_in[2];
    const float* W     = (const float*)d_in[3];
    const float* bias  = (const float*)d_in[4];
    const int*   row   = (const int*)d_in[5];
    const int*   col   = (const int*)d_in[6];
    float* out = (float*)d_out;

    int N = in_sizes[2] / 4;
    int E = in_sizes[5];

    int smem_bytes = SMEM_WORDS * sizeof(float);   // 216704
    cudaFuncSetAttribute(edge_kernel, cudaFuncAttributeMaxDynamicSharedMemorySize,
                         smem_bytes);

    zero_kernel<<<512, 256>>>(out, out_size, N);
    node_kernel<<<(N + 255) / 256, 256>>>(coord, cw, N);
    edge_kernel<<<148, NTHREADS, smem_bytes>>>(coord, attr, cw, W, bias, row, col, out, E);
    finalize_kernel<<<(N + 255) / 256, 256>>>(out, N);
}

// round 15
// speedup vs baseline: 1.0426x; 1.0426x over previous
#include <cuda_runtime.h>
#include <cuda_fp16.h>
#include <math.h>
#include <stdint.h>

#define NMAX 50000
#define DOUT 64
#define OSTRIDE 76
#define KCH16 17          // 17 k-chunks of 16 -> K = 272 (265 real + 7 zero pad)
#define KWH 148           // rad row stride in 32-bit words (296 halves); 148%32=20
#define WST 136           // W row stride in words; 136%32=8 -> conflict-free LDS.64
#define NPAIR 14
#define NTHREADS 896

// shared memory offsets (32-bit words)
#define OFF_W 0                     // 64*136        = 8704
#define OFF_RAD 8704                // 224*148       = 33152 -> 41856
#define OFF_ATT 41856               // 28 warps*256  =  7168 -> 49024 (double-buffered)
#define OFF_M 49024                 // 28 warps*32   =   896 -> 49920 (double-buffered)
#define OFF_RINV 49920              // 224 -> 50144
#define OFF_ROW 50144               // 224 -> 50368
#define OFF_BIAS 50368              // 64  -> 50432
#define SMEM_WORDS 50432            // *4 = 201728 bytes (< 227KB limit)

__device__ float g_lf[NMAX * 9];
__device__ float g_pooled[NMAX * 3];
__device__ float g_cnt[NMAX];

// ---------------------------------------------------------------------------
__device__ __forceinline__ void red4(float* p, float a, float b, float c, float d) {
    asm volatile("red.global.add.v4.f32 [%0], {%1,%2,%3,%4};"
                 :: "l"(p), "f"(a), "f"(b), "f"(c), "f"(d) : "memory");
}

// pack two fp32 into one fp16x2 word: lo <- a, hi <- b
__device__ __forceinline__ uint32_t f2h2(float lo, float hi) {
    uint32_t r;
    asm("cvt.rn.f16x2.f32 %0, %1, %2;" : "=r"(r) : "f"(hi), "f"(lo));
    return r;
}

// ---------------------------------------------------------------------------
__global__ void zero_kernel(float* out, int out_n, int n_nodes) {
    int i = blockIdx.x * blockDim.x + threadIdx.x;
    int stride = gridDim.x * blockDim.x;
    for (int k = i; k < out_n; k += stride) out[k] = 0.f;
    for (int k = i; k < n_nodes; k += stride) g_cnt[k] = 0.f;
}

// ---------------------------------------------------------------------------
__global__ void node_kernel(const float* __restrict__ coord,
                            const float* __restrict__ cw, int n) {
    int v = blockIdx.x * blockDim.x + threadIdx.x;
    if (v >= n) return;
    const float* cp = coord + v * 12;
    float cax = cp[0], cay = cp[1], caz = cp[2];
    float ccx = cp[3], ccy = cp[4], ccz = cp[5];
    float nnx = cp[6], nny = cp[7], nnz = cp[8];

    float xx = ccx - cax, xy = ccy - cay, xz = ccz - caz;
    float xn = sqrtf(xx * xx + xy * xy + xz * xz) + 1e-8f;
    xx /= xn; xy /= xn; xz /= xn;

    float tx = nnx - cax, ty = nny - cay, tz = nnz - caz;
    float d = tx * xx + ty * xy + tz * xz;
    float yx = tx - d * xx, yy = ty - d * xy, yz = tz - d * xz;
    float yn = sqrtf(yx * yx + yy * yy + yz * yz) + 1e-8f;
    yx /= yn; yy /= yn; yz /= yn;

    float zx = xy * yz - xz * yy;
    float zy = xz * yx - xx * yz;
    float zz = xx * yy - xy * yx;

    float* L = g_lf + v * 9;
    L[0] = xx; L[1] = yx; L[2] = zx;
    L[3] = xy; L[4] = yy; L[5] = zy;
    L[6] = xz; L[7] = yz; L[8] = zz;

    float px = 0.f, py = 0.f, pz = 0.f, cs = 0.f;
#pragma unroll
    for (int i = 0; i < 4; i++) {
        float m = (cw[v * 4 + i] != 0.f) ? 1.f : 0.f;
        cs += m;
        px += cp[i * 3 + 0] * m;
        py += cp[i * 3 + 1] * m;
        pz += cp[i * 3 + 2] * m;
    }
    g_pooled[v * 3 + 0] = px / cs;
    g_pooled[v * 3 + 1] = py / cs;
    g_pooled[v * 3 + 2] = pz / cs;
}

// ---------------------------------------------------------------------------
__device__ __forceinline__ void mma16(float& d0, float& d1, float& d2, float& d3,
                                      uint32_t a0, uint32_t a1, uint32_t a2, uint32_t a3,
                                      uint32_t b0, uint32_t b1) {
    asm volatile("mma.sync.aligned.m16n8k16.row.col.f32.f16.f16.f32 "
                 "{%0,%1,%2,%3}, {%4,%5,%6,%7}, {%8,%9}, {%0,%1,%2,%3};"
                 : "+f"(d0), "+f"(d1), "+f"(d2), "+f"(d3)
                 : "r"(a0), "r"(a1), "r"(a2), "r"(a3), "r"(b0), "r"(b1));
}

__device__ __forceinline__ void pair_bar(int pair) {
    asm volatile("bar.sync %0, 64;" :: "r"(pair + 1) : "memory");
}

// ---------------------------------------------------------------------------
// 14 independent 2-warp pipelines per CTA; fp16 GEMM operands, fp32 accum.
// Radial k-dim permuted (k' = b*16 + a) -> per-lane STS.128 writeout.
// W k-words interleaved in (tig, tig+4) pairs -> B fragments load as LDS.64,
// conflict-free with the WST=136 (== 8 mod 32) row stride.
__global__ void __launch_bounds__(NTHREADS, 1)
edge_kernel(const float* __restrict__ coord, const float* __restrict__ attr,
            const float* __restrict__ cw, const float* __restrict__ W,
            const float* __restrict__ bias, const int* __restrict__ row,
            const int* __restrict__ col, float* __restrict__ out, int E) {
    extern __shared__ float sm[];
    uint32_t* sWw  = (uint32_t*)(sm + OFF_W);      // W fp16: [o][paired kwords], stride WST
    __half*   sRadH = (__half*)(sm + OFF_RAD);     // rad fp16: rows of 296 halves
    float* sBias = sm + OFF_BIAS;

    int tid = threadIdx.x, warp = tid >> 5, lane = tid & 31;

    // Stage W: position p = kc*8 + tig*2 + sel holds k-word (kc*8 + tig + sel*4),
    // where each k-word packs halves k' = 2*kword, 2*kword+1 and the radial
    // part of k' is the permutation k' = b*16 + a  (orig k = (k'&15)*16 + k'>>4).
    for (int idx = tid; idx < 64 * 136; idx += NTHREADS) {
        int o = idx / 136, p = idx % 136;
        int kc = p >> 3, q = p & 7, tg = q >> 1, sel = q & 1;
        int kword = kc * 8 + tg + sel * 4;
        int kp0 = 2 * kword, kp1 = 2 * kword + 1;
        float f0 = 0.f, f1 = 0.f;
        if (kp0 < 256)      f0 = W[o * 273 + ((kp0 & 15) * 16 + (kp0 >> 4))];
        else if (kp0 < 265) f0 = W[o * 273 + kp0 + 8];
        if (kp1 < 256)      f1 = W[o * 273 + ((kp1 & 15) * 16 + (kp1 >> 4))];
        else if (kp1 < 265) f1 = W[o * 273 + kp1 + 8];
        __half2 h = __floats2half2_rn(f0, f1);
        sWw[o * WST + p] = *(uint32_t*)&h;
    }
    // Zero rad k-pad (halves 265..295) ONCE — never overwritten afterwards.
    for (int idx = tid; idx < 224 * 31; idx += NTHREADS) {
        int rrow = idx / 31, kk = 265 + idx % 31;
        sRadH[rrow * 296 + kk] = __ushort_as_half(0);
    }
    if (tid < 64) sBias[tid] = bias[tid];
    __syncthreads();

    const int pair = warp >> 1;         // 0..13
    const int win  = warp & 1;
    const int g = lane >> 2, tig = lane & 3;
    const int b16 = lane & 15, half = lane >> 4;
    const int oh = win * 32;            // this warp's output-column half

    uint32_t* radw   = (uint32_t*)(sm + OFF_RAD) + pair * 16 * KWH;
    __half*   sRadP  = sRadH + pair * 16 * 296;
    float* sRinvP = sm + OFF_RINV + pair * 16;
    int*   sRowP  = (int*)(sm + OFF_ROW) + pair * 16;
    float* sAttW  = sm + OFF_ATT + warp * 256;   // 2 slots x [attr_r(64)|attr_c(64)]
    float* sMW    = sm + OFF_M + warp * 32;      // 2 slots x 16
    const int mi = (lane >> 2) & 3, mj = lane & 3;
    const int hb = 2 * half;            // float4 base for this half's ar rows
    const int wbase = b16 * 8 + half * 4;  // this lane's rad word base (16B aligned)

    int gpair  = blockIdx.x * NPAIR + pair;
    int npairs = gridDim.x * NPAIR;
    int ngroups = (E + 15) >> 4;

    for (int grp = gpair; grp < ngroups; grp += npairs) {
        // wait until the partner warp finished reading rad of the previous group
        pair_bar(pair);

        // ================= phase 1: 8 edges per warp =================
        int e0g = grp * 16 + win * 8;
        int rc = 0;
        {
            int e = e0g + (lane & 7);
            if (e < E) rc = (lane < 16) ? row[e] : col[e];
        }
        if (lane < 8) sRowP[win * 8 + lane] = rc;

        float ssq[8];
#pragma unroll
        for (int h4 = 0; h4 < 2; h4++) {
            // ---- batched prefetch of 4 edges (MLP=4) ----
            float4 av[4];
            float gv[4], lfv[4], pv[4];
            int rr[4];
#pragma unroll
            for (int u = 0; u < 4; u++) {
                int t = h4 * 4 + u;
                int r = __shfl_sync(0xffffffffu, rc, t);
                int c = __shfl_sync(0xffffffffu, rc, 16 + t);
                rr[u] = r;
                int nn = (lane < 16) ? r : c;
                av[u] = __ldg((const float4*)(attr + nn * 64) + b16);
                const float* gp;
                if (lane < 12)      gp = coord + r * 12 + lane;
                else if (lane < 24) gp = coord + c * 12 + (lane - 12);
                else if (lane < 28) gp = cw + r * 4 + (lane - 24);
                else                gp = cw + c * 4 + (lane - 28);
                gv[u] = __ldg(gp);
                lfv[u] = (lane < 9)
                       ? g_lf[r * 9 + lane] + g_lf[c * 9 + lane] : 0.f;
                pv[u] = (lane < 12) ? g_pooled[c * 3 + lane % 3] : 0.f;
            }

            // ---- process the 4 edges (double-buffered staging) ----
#pragma unroll
            for (int u = 0; u < 4; u++) {
                int t = h4 * 4 + u;
                float* slot = sAttW + (t & 1) * 128;
                float* sMs  = sMW + (t & 1) * 16;
                ((float4*)slot)[lane] = av[u];

                float gvu = gv[u];
                float rx = __shfl_sync(0xffffffffu, gvu, 3 * mi);
                float ry = __shfl_sync(0xffffffffu, gvu, 3 * mi + 1);
                float rz = __shfl_sync(0xffffffffu, gvu, 3 * mi + 2);
                float cx = __shfl_sync(0xffffffffu, gvu, 12 + 3 * mj);
                float cy = __shfl_sync(0xffffffffu, gvu, 13 + 3 * mj);
                float cz = __shfl_sync(0xffffffffu, gvu, 14 + 3 * mj);
                float wr = __shfl_sync(0xffffffffu, gvu, 24 + mi);
                float wc = __shfl_sync(0xffffffffu, gvu, 28 + mj);
                if (lane < 16) {
                    float dx = rx - cx, dy = ry - cy, dz = rz - cz;
                    sMs[lane] = sqrtf(dx * dx + dy * dy + dz * dz) * wr * wc;
                }
                __syncwarp();

                // ---- vectorized smem reads: M as 4x LDS.128 ----
                const float4* m4 = (const float4*)sMs;
                float4 M0 = m4[0], M1 = m4[1], M2 = m4[2], M3 = m4[3];

                const float* s_ac = slot + 64;
                float a0 = s_ac[b16], a1 = s_ac[16 + b16];
                float a2 = s_ac[32 + b16], a3 = s_ac[48 + b16];
                float tmp0 = M0.x * a0 + M0.y * a1 + M0.z * a2 + M0.w * a3;
                float tmp1 = M1.x * a0 + M1.y * a1 + M1.z * a2 + M1.w * a3;
                float tmp2 = M2.x * a0 + M2.y * a1 + M2.z * a2 + M2.w * a3;
                float tmp3 = M3.x * a0 + M3.y * a1 + M3.z * a2 + M3.w * a3;

                // ---- ar rows as 8x LDS.128 (broadcast within half) ----
                const float4* slot4 = (const float4*)slot;
                float4 r0a = slot4[hb],      r0b = slot4[hb + 1];
                float4 r1a = slot4[4 + hb],  r1b = slot4[4 + hb + 1];
                float4 r2a = slot4[8 + hb],  r2b = slot4[8 + hb + 1];
                float4 r3a = slot4[12 + hb], r3b = slot4[12 + hb + 1];

                float va[8];
                va[0] = r0a.x * tmp0 + r1a.x * tmp1 + r2a.x * tmp2 + r3a.x * tmp3;
                va[1] = r0a.y * tmp0 + r1a.y * tmp1 + r2a.y * tmp2 + r3a.y * tmp3;
                va[2] = r0a.z * tmp0 + r1a.z * tmp1 + r2a.z * tmp2 + r3a.z * tmp3;
                va[3] = r0a.w * tmp0 + r1a.w * tmp1 + r2a.w * tmp2 + r3a.w * tmp3;
                va[4] = r0b.x * tmp0 + r1b.x * tmp1 + r2b.x * tmp2 + r3b.x * tmp3;
                va[5] = r0b.y * tmp0 + r1b.y * tmp1 + r2b.y * tmp2 + r3b.y * tmp3;
                va[6] = r0b.z * tmp0 + r1b.z * tmp1 + r2b.z * tmp2 + r3b.z * tmp3;
                va[7] = r0b.w * tmp0 + r1b.w * tmp1 + r2b.w * tmp2 + r3b.w * tmp3;

                // ---- packed radial writeout: 4x cvt.f16x2 + one STS.128 ----
                uint32_t* rw = radw + (win * 8 + t) * KWH;
                uint4 pk;
                pk.x = f2h2(va[0], va[1]);
                pk.y = f2h2(va[2], va[3]);
                pk.z = f2h2(va[4], va[5]);
                pk.w = f2h2(va[6], va[7]);
                *(uint4*)(rw + wbase) = pk;

                float part = va[0]*va[0] + va[1]*va[1] + va[2]*va[2] + va[3]*va[3]
                           + va[4]*va[4] + va[5]*va[5] + va[6]*va[6] + va[7]*va[7];

                __half* rrow = sRadP + (win * 8 + t) * 296;
                if (lane < 9) {
                    rrow[256 + lane] = __float2half_rn(lfv[u]);
                    part += lfv[u] * lfv[u];
                }
                ssq[t] = part;

                // ---- coord aggregation: pack 12 diffs into 3 red.v4 + cnt ----
                float dco = (lane < 12) ? (gvu - pv[u]) : 0.f;
                float q0 = __shfl_sync(0xffffffffu, dco, (4 * lane) & 31);
                float q1 = __shfl_sync(0xffffffffu, dco, (4 * lane + 1) & 31);
                float q2 = __shfl_sync(0xffffffffu, dco, (4 * lane + 2) & 31);
                float q3 = __shfl_sync(0xffffffffu, dco, (4 * lane + 3) & 31);
                if (e0g + t < E) {
                    if (lane < 3)
                        red4(out + rr[u] * OSTRIDE + 64 + 4 * lane, q0, q1, q2, q3);
                    else if (lane == 3)
                        atomicAdd(&g_cnt[rr[u]], 1.f);
                }
            }
        }

        // deferred reductions: 8 independent shuffle trees, pipelined
#pragma unroll
        for (int t = 0; t < 8; t++) {
            float s = ssq[t];
            s += __shfl_xor_sync(0xffffffffu, s, 16);
            s += __shfl_xor_sync(0xffffffffu, s, 8);
            s += __shfl_xor_sync(0xffffffffu, s, 4);
            s += __shfl_xor_sync(0xffffffffu, s, 2);
            s += __shfl_xor_sync(0xffffffffu, s, 1);
            if (lane == t) sRinvP[win * 8 + t] = __frcp_rn(sqrtf(s) + 1.f);
        }
        pair_bar(pair);   // rad/rinv/row of both warps visible to the pair

        // ===== phase 2: fp16 MMA (m16n8k16), 16 edges x 32 outs per warp ====
        float acc[4][4];
#pragma unroll
        for (int n = 0; n < 4; n++)
#pragma unroll
            for (int q = 0; q < 4; q++) acc[n][q] = 0.f;

        const uint32_t* aB = radw + g * KWH + tig;
        const uint32_t* bB = sWw + (oh + g) * WST + tig * 2;

#pragma unroll 2
        for (int kc = 0; kc < KCH16; kc++) {
            int k0 = kc * 8;
            uint32_t A0 = aB[k0];
            uint32_t A1 = aB[8 * KWH + k0];
            uint32_t A2 = aB[k0 + 4];
            uint32_t A3 = aB[8 * KWH + k0 + 4];
#pragma unroll
            for (int n = 0; n < 4; n++) {
                uint2 bv = *(const uint2*)(bB + n * 8 * WST + k0);
                mma16(acc[n][0], acc[n][1], acc[n][2], acc[n][3],
                      A0, A1, A2, A3, bv.x, bv.y);
            }
        }

        // ====== epilogue: (acc + b) * rinv -> paired red.v4 scatter ==========
        {
            int el0 = g, el1 = 8 + g;
            bool v0 = (grp * 16 + el0) < E;
            bool v1 = (grp * 16 + el1) < E;
            float ri0 = sRinvP[el0], ri1 = sRinvP[el1];
            float* ob0 = out + sRowP[el0] * OSTRIDE;
            float* ob1 = out + sRowP[el1] * OSTRIDE;
            bool emit = ((tig & 1) == 0);
#pragma unroll
            for (int n = 0; n < 4; n++) {
                int o = oh + n * 8 + 2 * tig;
                float bo0 = sBias[o], bo1 = sBias[o + 1];
                float x0 = (acc[n][0] + bo0) * ri0;
                float x1 = (acc[n][1] + bo1) * ri0;
                float z0 = (acc[n][2] + bo0) * ri1;
                float z1 = (acc[n][3] + bo1) * ri1;
                float px0 = __shfl_xor_sync(0xffffffffu, x0, 1);
                float px1 = __shfl_xor_sync(0xffffffffu, x1, 1);
                float pz0 = __shfl_xor_sync(0xffffffffu, z0, 1);
                float pz1 = __shfl_xor_sync(0xffffffffu, z1, 1);
                if (emit) {
                    if (v0) red4(ob0 + o, x0, x1, px0, px1);
                    if (v1) red4(ob1 + o, z0, z1, pz0, pz1);
                }
            }
        }
    }
}

// ---------------------------------------------------------------------------
__global__ void finalize_kernel(float* out, int n) {
    int v = blockIdx.x * blockDim.x + threadIdx.x;
    if (v >= n) return;
    float cf = 1.f / fmaxf(g_cnt[v], 1.f);
    float* p = out + v * OSTRIDE + 64;
#pragma unroll
    for (int d = 0; d < 12; d++) p[d] *= cf;
}

// ---------------------------------------------------------------------------
extern "C" void kernel_launch(void* const* d_in, const int* in_sizes, int n_in,
                              void* d_out, int out_size) {
    const float* coord = (const float*)d_in[0];
    const float* attr  = (const float*)d_in[1];
    const float* cw    = (const float*)d_in[2];
    const float* W     = (const float*)d_in[3];
    const float* bias  = (const float*)d_in[4];
    const int*   row   = (const int*)d_in[5];
    const int*   col   = (const int*)d_in[6];
    float* out = (float*)d_out;

    int N = in_sizes[2] / 4;
    int E = in_sizes[5];

    int smem_bytes = SMEM_WORDS * sizeof(float);   // 201728
    cudaFuncSetAttribute(edge_kernel, cudaFuncAttributeMaxDynamicSharedMemorySize,
                         smem_bytes);

    zero_kernel<<<512, 256>>>(out, out_size, N);
    node_kernel<<<(N + 255) / 256, 256>>>(coord, cw, N);
    edge_kernel<<<148, NTHREADS, smem_bytes>>>(coord, attr, cw, W, bias, row, col, out, E);
    finalize_kernel<<<(N + 255) / 256, 256>>>(out, N);
}

// round 16
// speedup vs baseline: 1.0497x; 1.0068x over previous
#include <cuda_runtime.h>
#include <cuda_fp16.h>
#include <math.h>
#include <stdint.h>

#define NMAX 50000
#define DOUT 64
#define OSTRIDE 76
#define KCH16 17          // 17 k-chunks of 16 -> K = 272 (265 real + 7 zero pad)
#define KWH 148           // rad row stride in 32-bit words (296 halves); 148%32=20
#define WST 136           // W row stride in words; 136%32=8 -> conflict-free LDS.64
#define NPAIR 14
#define NTHREADS 896

// shared memory offsets (32-bit words)
#define OFF_W 0                     // 64*136        = 8704
#define OFF_RAD 8704                // 224*148       = 33152 -> 41856
#define OFF_ATT 41856               // 28 warps*256  =  7168 -> 49024 (double-buffered)
#define OFF_M 49024                 // 28 warps*32   =   896 -> 49920 (double-buffered)
#define OFF_RINV 49920              // 224 -> 50144
#define OFF_ROW 50144               // 224 -> 50368
#define OFF_BIAS 50368              // 64  -> 50432
#define OFF_NEXT 50432              // 16 (next-group slot per pair) -> 50448
#define SMEM_WORDS 50448            // *4 = 201792 bytes (< 227KB limit)

__device__ float g_lf[NMAX * 9];
__device__ float g_pooled[NMAX * 3];
__device__ float g_cnt[NMAX];
__device__ int   g_ctr;

// ---------------------------------------------------------------------------
__device__ __forceinline__ void red4(float* p, float a, float b, float c, float d) {
    asm volatile("red.global.add.v4.f32 [%0], {%1,%2,%3,%4};"
                 :: "l"(p), "f"(a), "f"(b), "f"(c), "f"(d) : "memory");
}

// pack two fp32 into one fp16x2 word: lo <- a, hi <- b
__device__ __forceinline__ uint32_t f2h2(float lo, float hi) {
    uint32_t r;
    asm("cvt.rn.f16x2.f32 %0, %1, %2;" : "=r"(r) : "f"(hi), "f"(lo));
    return r;
}

// ldmatrix x4: A-fragment for mma.m16n8k16 (rows 0..15, two 8-half column blocks)
__device__ __forceinline__ void ldmA(uint32_t& r0, uint32_t& r1, uint32_t& r2,
                                     uint32_t& r3, uint32_t saddr) {
    asm volatile("ldmatrix.sync.aligned.m8n8.x4.shared.b16 {%0,%1,%2,%3}, [%4];"
                 : "=r"(r0), "=r"(r1), "=r"(r2), "=r"(r3) : "r"(saddr));
}

// ---------------------------------------------------------------------------
// Fused prologue: zero output + counters, compute local frames + pooled coords.
__global__ void zeronode_kernel(float* out, int out_n,
                                const float* __restrict__ coord,
                                const float* __restrict__ cw, int n) {
    int i = blockIdx.x * blockDim.x + threadIdx.x;
    int stride = gridDim.x * blockDim.x;
    if (i == 0) g_ctr = 0;
    for (int k = i; k < out_n; k += stride) out[k] = 0.f;
    for (int k = i; k < n; k += stride) g_cnt[k] = 0.f;

    int v = i;
    if (v >= n) return;
    const float* cp = coord + v * 12;
    float cax = cp[0], cay = cp[1], caz = cp[2];
    float ccx = cp[3], ccy = cp[4], ccz = cp[5];
    float nnx = cp[6], nny = cp[7], nnz = cp[8];

    float xx = ccx - cax, xy = ccy - cay, xz = ccz - caz;
    float xn = sqrtf(xx * xx + xy * xy + xz * xz) + 1e-8f;
    xx /= xn; xy /= xn; xz /= xn;

    float tx = nnx - cax, ty = nny - cay, tz = nnz - caz;
    float d = tx * xx + ty * xy + tz * xz;
    float yx = tx - d * xx, yy = ty - d * xy, yz = tz - d * xz;
    float yn = sqrtf(yx * yx + yy * yy + yz * yz) + 1e-8f;
    yx /= yn; yy /= yn; yz /= yn;

    float zx = xy * yz - xz * yy;
    float zy = xz * yx - xx * yz;
    float zz = xx * yy - xy * yx;

    float* L = g_lf + v * 9;
    L[0] = xx; L[1] = yx; L[2] = zx;
    L[3] = xy; L[4] = yy; L[5] = zy;
    L[6] = xz; L[7] = yz; L[8] = zz;

    float px = 0.f, py = 0.f, pz = 0.f, cs = 0.f;
#pragma unroll
    for (int q = 0; q < 4; q++) {
        float m = (cw[v * 4 + q] != 0.f) ? 1.f : 0.f;
        cs += m;
        px += cp[q * 3 + 0] * m;
        py += cp[q * 3 + 1] * m;
        pz += cp[q * 3 + 2] * m;
    }
    g_pooled[v * 3 + 0] = px / cs;
    g_pooled[v * 3 + 1] = py / cs;
    g_pooled[v * 3 + 2] = pz / cs;
}

// ---------------------------------------------------------------------------
__device__ __forceinline__ void mma16(float& d0, float& d1, float& d2, float& d3,
                                      uint32_t a0, uint32_t a1, uint32_t a2, uint32_t a3,
                                      uint32_t b0, uint32_t b1) {
    asm volatile("mma.sync.aligned.m16n8k16.row.col.f32.f16.f16.f32 "
                 "{%0,%1,%2,%3}, {%4,%5,%6,%7}, {%8,%9}, {%0,%1,%2,%3};"
                 : "+f"(d0), "+f"(d1), "+f"(d2), "+f"(d3)
                 : "r"(a0), "r"(a1), "r"(a2), "r"(a3), "r"(b0), "r"(b1));
}

__device__ __forceinline__ void pair_bar(int pair) {
    asm volatile("bar.sync %0, 64;" :: "r"(pair + 1) : "memory");
}

// ---------------------------------------------------------------------------
// 14 independent 2-warp pipelines per CTA; fp16 GEMM operands, fp32 accum.
// Groups are distributed DYNAMICALLY via a global ticket counter (grab is
// issued after bar B, consumed after the next bar A -> race-free + hidden).
__global__ void __launch_bounds__(NTHREADS, 1)
edge_kernel(const float* __restrict__ coord, const float* __restrict__ attr,
            const float* __restrict__ cw, const float* __restrict__ W,
            const float* __restrict__ bias, const int* __restrict__ row,
            const int* __restrict__ col, float* __restrict__ out, int E) {
    extern __shared__ float sm[];
    uint32_t* sWw  = (uint32_t*)(sm + OFF_W);      // W fp16: [o][paired kwords], stride WST
    __half*   sRadH = (__half*)(sm + OFF_RAD);     // rad fp16: rows of 296 halves
    float* sBias = sm + OFF_BIAS;
    int*   sNext = (int*)(sm + OFF_NEXT);

    int tid = threadIdx.x, warp = tid >> 5, lane = tid & 31;

    // Stage W: position p = kc*8 + tig*2 + sel holds k-word (kc*8 + tig + sel*4);
    // radial part of k' is the permutation k' = b*16 + a (orig k = (k'&15)*16 + k'>>4).
    for (int idx = tid; idx < 64 * 136; idx += NTHREADS) {
        int o = idx / 136, p = idx % 136;
        int kc = p >> 3, q = p & 7, tg = q >> 1, sel = q & 1;
        int kword = kc * 8 + tg + sel * 4;
        int kp0 = 2 * kword, kp1 = 2 * kword + 1;
        float f0 = 0.f, f1 = 0.f;
        if (kp0 < 256)      f0 = W[o * 273 + ((kp0 & 15) * 16 + (kp0 >> 4))];
        else if (kp0 < 265) f0 = W[o * 273 + kp0 + 8];
        if (kp1 < 256)      f1 = W[o * 273 + ((kp1 & 15) * 16 + (kp1 >> 4))];
        else if (kp1 < 265) f1 = W[o * 273 + kp1 + 8];
        __half2 h = __floats2half2_rn(f0, f1);
        sWw[o * WST + p] = *(uint32_t*)&h;
    }
    // Zero rad k-pad (halves 265..295) ONCE — never overwritten afterwards.
    for (int idx = tid; idx < 224 * 31; idx += NTHREADS) {
        int rrow = idx / 31, kk = 265 + idx % 31;
        sRadH[rrow * 296 + kk] = __ushort_as_half(0);
    }
    if (tid < 64) sBias[tid] = bias[tid];
    __syncthreads();

    const int pair = warp >> 1;         // 0..13
    const int win  = warp & 1;
    const int g = lane >> 2, tig = lane & 3;
    const int b16 = lane & 15, half = lane >> 4;
    const int oh = win * 32;            // this warp's output-column half

    uint32_t* radw   = (uint32_t*)(sm + OFF_RAD) + pair * 16 * KWH;
    __half*   sRadP  = sRadH + pair * 16 * 296;
    float* sRinvP = sm + OFF_RINV + pair * 16;
    int*   sRowP  = (int*)(sm + OFF_ROW) + pair * 16;
    float* sAttW  = sm + OFF_ATT + warp * 256;   // 2 slots x [attr_r(64)|attr_c(64)]
    float* sMW    = sm + OFF_M + warp * 32;      // 2 slots x 16
    const int mi = (lane >> 2) & 3, mj = lane & 3;
    const int hb = 2 * half;            // float4 base for this half's ar rows
    const int wbase = b16 * 8 + half * 4;  // this lane's rad word base (16B aligned)

    // ldmatrix A-fragment base address (shared space): row = lane&15, colhalf = lane>>4
    const uint32_t aLdBase = (uint32_t)__cvta_generic_to_shared(radw)
                           + (uint32_t)(lane & 15) * (KWH * 4) + (uint32_t)(lane >> 4) * 16;

    int ngroups = (E + 15) >> 4;

    // initial ticket grab
    if (win == 0 && lane == 0) sNext[pair] = atomicAdd(&g_ctr, 1);

    for (;;) {
        pair_bar(pair);                 // bar A: rad free + sNext visible
        int grp = sNext[pair];
        if (grp >= ngroups) break;

        // ================= phase 1: 8 edges per warp =================
        int e0g = grp * 16 + win * 8;
        int rc = 0;
        {
            int e = e0g + (lane & 7);
            if (e < E) rc = (lane < 16) ? row[e] : col[e];
        }
        if (lane < 8) sRowP[win * 8 + lane] = rc;

        float ssq[8];
#pragma unroll
        for (int h4 = 0; h4 < 2; h4++) {
            // ---- batched prefetch of 4 edges (MLP=4) ----
            float4 av[4];
            float gv[4], lfv[4], pv[4];
            int rr[4];
#pragma unroll
            for (int u = 0; u < 4; u++) {
                int t = h4 * 4 + u;
                int r = __shfl_sync(0xffffffffu, rc, t);
                int c = __shfl_sync(0xffffffffu, rc, 16 + t);
                rr[u] = r;
                int nn = (lane < 16) ? r : c;
                av[u] = __ldg((const float4*)(attr + nn * 64) + b16);
                const float* gp;
                if (lane < 12)      gp = coord + r * 12 + lane;
                else if (lane < 24) gp = coord + c * 12 + (lane - 12);
                else if (lane < 28) gp = cw + r * 4 + (lane - 24);
                else                gp = cw + c * 4 + (lane - 28);
                gv[u] = __ldg(gp);
                lfv[u] = (lane < 9)
                       ? g_lf[r * 9 + lane] + g_lf[c * 9 + lane] : 0.f;
                pv[u] = (lane < 12) ? g_pooled[c * 3 + lane % 3] : 0.f;
            }

            // ---- process the 4 edges (double-buffered staging) ----
#pragma unroll
            for (int u = 0; u < 4; u++) {
                int t = h4 * 4 + u;
                float* slot = sAttW + (t & 1) * 128;
                float* sMs  = sMW + (t & 1) * 16;
                ((float4*)slot)[lane] = av[u];

                float gvu = gv[u];
                float rx = __shfl_sync(0xffffffffu, gvu, 3 * mi);
                float ry = __shfl_sync(0xffffffffu, gvu, 3 * mi + 1);
                float rz = __shfl_sync(0xffffffffu, gvu, 3 * mi + 2);
                float cx = __shfl_sync(0xffffffffu, gvu, 12 + 3 * mj);
                float cy = __shfl_sync(0xffffffffu, gvu, 13 + 3 * mj);
                float cz = __shfl_sync(0xffffffffu, gvu, 14 + 3 * mj);
                float wr = __shfl_sync(0xffffffffu, gvu, 24 + mi);
                float wc = __shfl_sync(0xffffffffu, gvu, 28 + mj);
                if (lane < 16) {
                    float dx = rx - cx, dy = ry - cy, dz = rz - cz;
                    sMs[lane] = sqrtf(dx * dx + dy * dy + dz * dz) * wr * wc;
                }
                __syncwarp();

                // ---- vectorized smem reads: M as 4x LDS.128 ----
                const float4* m4 = (const float4*)sMs;
                float4 M0 = m4[0], M1 = m4[1], M2 = m4[2], M3 = m4[3];

                const float* s_ac = slot + 64;
                float a0 = s_ac[b16], a1 = s_ac[16 + b16];
                float a2 = s_ac[32 + b16], a3 = s_ac[48 + b16];
                float tmp0 = M0.x * a0 + M0.y * a1 + M0.z * a2 + M0.w * a3;
                float tmp1 = M1.x * a0 + M1.y * a1 + M1.z * a2 + M1.w * a3;
                float tmp2 = M2.x * a0 + M2.y * a1 + M2.z * a2 + M2.w * a3;
                float tmp3 = M3.x * a0 + M3.y * a1 + M3.z * a2 + M3.w * a3;

                // ---- ar rows as 8x LDS.128 (broadcast within half) ----
                const float4* slot4 = (const float4*)slot;
                float4 r0a = slot4[hb],      r0b = slot4[hb + 1];
                float4 r1a = slot4[4 + hb],  r1b = slot4[4 + hb + 1];
                float4 r2a = slot4[8 + hb],  r2b = slot4[8 + hb + 1];
                float4 r3a = slot4[12 + hb], r3b = slot4[12 + hb + 1];

                float va[8];
                va[0] = r0a.x * tmp0 + r1a.x * tmp1 + r2a.x * tmp2 + r3a.x * tmp3;
                va[1] = r0a.y * tmp0 + r1a.y * tmp1 + r2a.y * tmp2 + r3a.y * tmp3;
                va[2] = r0a.z * tmp0 + r1a.z * tmp1 + r2a.z * tmp2 + r3a.z * tmp3;
                va[3] = r0a.w * tmp0 + r1a.w * tmp1 + r2a.w * tmp2 + r3a.w * tmp3;
                va[4] = r0b.x * tmp0 + r1b.x * tmp1 + r2b.x * tmp2 + r3b.x * tmp3;
                va[5] = r0b.y * tmp0 + r1b.y * tmp1 + r2b.y * tmp2 + r3b.y * tmp3;
                va[6] = r0b.z * tmp0 + r1b.z * tmp1 + r2b.z * tmp2 + r3b.z * tmp3;
                va[7] = r0b.w * tmp0 + r1b.w * tmp1 + r2b.w * tmp2 + r3b.w * tmp3;

                // ---- packed radial writeout: 4x cvt.f16x2 + one STS.128 ----
                uint32_t* rw = radw + (win * 8 + t) * KWH;
                uint4 pk;
                pk.x = f2h2(va[0], va[1]);
                pk.y = f2h2(va[2], va[3]);
                pk.z = f2h2(va[4], va[5]);
                pk.w = f2h2(va[6], va[7]);
                *(uint4*)(rw + wbase) = pk;

                float part = va[0]*va[0] + va[1]*va[1] + va[2]*va[2] + va[3]*va[3]
                           + va[4]*va[4] + va[5]*va[5] + va[6]*va[6] + va[7]*va[7];

                __half* rrow = sRadP + (win * 8 + t) * 296;
                if (lane < 9) {
                    rrow[256 + lane] = __float2half_rn(lfv[u]);
                    part += lfv[u] * lfv[u];
                }
                ssq[t] = part;

                // ---- coord aggregation: pack 12 diffs into 3 red.v4 + cnt ----
                float dco = (lane < 12) ? (gvu - pv[u]) : 0.f;
                float q0 = __shfl_sync(0xffffffffu, dco, (4 * lane) & 31);
                float q1 = __shfl_sync(0xffffffffu, dco, (4 * lane + 1) & 31);
                float q2 = __shfl_sync(0xffffffffu, dco, (4 * lane + 2) & 31);
                float q3 = __shfl_sync(0xffffffffu, dco, (4 * lane + 3) & 31);
                if (e0g + t < E) {
                    if (lane < 3)
                        red4(out + rr[u] * OSTRIDE + 64 + 4 * lane, q0, q1, q2, q3);
                    else if (lane == 3)
                        atomicAdd(&g_cnt[rr[u]], 1.f);
                }
            }
        }

        // deferred reductions: 8 independent shuffle trees, pipelined
#pragma unroll
        for (int t = 0; t < 8; t++) {
            float s = ssq[t];
            s += __shfl_xor_sync(0xffffffffu, s, 16);
            s += __shfl_xor_sync(0xffffffffu, s, 8);
            s += __shfl_xor_sync(0xffffffffu, s, 4);
            s += __shfl_xor_sync(0xffffffffu, s, 2);
            s += __shfl_xor_sync(0xffffffffu, s, 1);
            if (lane == t) sRinvP[win * 8 + t] = __frcp_rn(sqrtf(s) + 1.f);
        }
        pair_bar(pair);   // bar B: rad/rinv/row of both warps visible to the pair

        // grab next ticket; hidden behind phase 2, consumed after next bar A
        if (win == 0 && lane == 0) sNext[pair] = atomicAdd(&g_ctr, 1);

        // ===== phase 2: fp16 MMA (m16n8k16), 16 edges x 32 outs per warp ====
        float acc[4][4];
#pragma unroll
        for (int n = 0; n < 4; n++)
#pragma unroll
            for (int q = 0; q < 4; q++) acc[n][q] = 0.f;

        const uint32_t* bB = sWw + (oh + g) * WST + tig * 2;

#pragma unroll 2
        for (int kc = 0; kc < KCH16; kc++) {
            int k0 = kc * 8;
            uint32_t A0, A1, A2, A3;
            ldmA(A0, A1, A2, A3, aLdBase + kc * 32);
#pragma unroll
            for (int n = 0; n < 4; n++) {
                uint2 bv = *(const uint2*)(bB + n * 8 * WST + k0);
                mma16(acc[n][0], acc[n][1], acc[n][2], acc[n][3],
                      A0, A1, A2, A3, bv.x, bv.y);
            }
        }

        // ====== epilogue: (acc + b) * rinv -> paired red.v4 scatter ==========
        {
            int el0 = g, el1 = 8 + g;
            bool v0 = (grp * 16 + el0) < E;
            bool v1 = (grp * 16 + el1) < E;
            float ri0 = sRinvP[el0], ri1 = sRinvP[el1];
            float* ob0 = out + sRowP[el0] * OSTRIDE;
            float* ob1 = out + sRowP[el1] * OSTRIDE;
            bool emit = ((tig & 1) == 0);
#pragma unroll
            for (int n = 0; n < 4; n++) {
                int o = oh + n * 8 + 2 * tig;
                float bo0 = sBias[o], bo1 = sBias[o + 1];
                float x0 = (acc[n][0] + bo0) * ri0;
                float x1 = (acc[n][1] + bo1) * ri0;
                float z0 = (acc[n][2] + bo0) * ri1;
                float z1 = (acc[n][3] + bo1) * ri1;
                float px0 = __shfl_xor_sync(0xffffffffu, x0, 1);
                float px1 = __shfl_xor_sync(0xffffffffu, x1, 1);
                float pz0 = __shfl_xor_sync(0xffffffffu, z0, 1);
                float pz1 = __shfl_xor_sync(0xffffffffu, z1, 1);
                if (emit) {
                    if (v0) red4(ob0 + o, x0, x1, px0, px1);
                    if (v1) red4(ob1 + o, z0, z1, pz0, pz1);
                }
            }
        }
    }
}

// ---------------------------------------------------------------------------
__global__ void finalize_kernel(float* out, int n) {
    int v = blockIdx.x * blockDim.x + threadIdx.x;
    if (v >= n) return;
    float cf = 1.f / fmaxf(g_cnt[v], 1.f);
    float* p = out + v * OSTRIDE + 64;
#pragma unroll
    for (int d = 0; d < 12; d++) p[d] *= cf;
}

// ---------------------------------------------------------------------------
extern "C" void kernel_launch(void* const* d_in, const int* in_sizes, int n_in,
                              void* d_out, int out_size) {
    const float* coord = (const float*)d_in[0];
    const float* attr  = (const float*)d_in[1];
    const float* cw    = (const float*)d_in[2];
    const float* W     = (const float*)d_in[3];
    const float* bias  = (const float*)d_in[4];
    const int*   row   = (const int*)d_in[5];
    const int*   col   = (const int*)d_in[6];
    float* out = (float*)d_out;

    int N = in_sizes[2] / 4;
    int E = in_sizes[5];

    int smem_bytes = SMEM_WORDS * sizeof(float);   // 201792
    cudaFuncSetAttribute(edge_kernel, cudaFuncAttributeMaxDynamicSharedMemorySize,
                         smem_bytes);

    zeronode_kernel<<<512, 256>>>(out, out_size, coord, cw, N);
    edge_kernel<<<148, NTHREADS, smem_bytes>>>(coord, attr, cw, W, bias, row, col, out, E);
    finalize_kernel<<<(N + 255) / 256, 256>>>(out, N);
}